// round 16
// baseline (speedup 1.0000x reference)
#include <cuda_runtime.h>
#include <cuda_bf16.h>
#include <math.h>
#include <stdint.h>

// ---------------- problem constants ----------------
#define BATCH 4
#define CCH   512
#define C8    64
#define NPIX  4096           // 64*64
#define NKT   32             // key tiles of 128 in PAM
#define SHIFT 16.0f          // fixed softmax shift (energy std ~8, |max|<50)
#define STG   4              // cp.async pipeline stages in gemm_b16

// ---------------- scratch (device globals; allocation-free) ----------------
__device__ float g_sump[BATCH * NKT * NPIX];
__device__ float g_ec[BATCH * CCH * CCH];                 // CAM energy fp32
__device__ float g_outp[BATCH * CCH * NPIX];              // PAM out (pre-gamma)
__device__ float g_qkc[BATCH * 2 * C8 * NPIX];            // CAM q||k fp32 [128, N]
__device__ float g_wck[2 * C8 * CCH];                     // CAM wq||wk fp32
__device__ float g_bck[2 * C8];
__device__ float g_bpk[2 * C8];
__device__ __nv_bfloat16 g_wpk[2 * C8 * CCH];             // PAM wq||wk bf16
__device__ __nv_bfloat16 g_wvp[CCH * CCH];                // PAM wv bf16
__device__ __nv_bfloat16 g_wvc[CCH * CCH];                // CAM wv bf16
__device__ __nv_bfloat16 g_qkp[BATCH * 2 * C8 * NPIX];    // PAM q||k bf16 [128, N]
__device__ __nv_bfloat16 g_xb [BATCH * CCH * NPIX];       // x in bf16
__device__ __nv_bfloat16 g_vp [BATCH * CCH * NPIX];       // PAM V, [C,N] bf16
__device__ __nv_bfloat16 g_vcT[BATCH * NPIX * CCH];       // CAM V, [N,C] bf16
__device__ __nv_bfloat16 g_pt[(size_t)BATCH * NPIX * NPIX]; // PAM p~ bf16
__device__ __nv_bfloat16 g_ecb[BATCH * CCH * CCH];        // CAM attn bf16

#define MMA_TF32(acc, af, bf)                                               \
    asm volatile(                                                           \
        "mma.sync.aligned.m16n8k8.row.col.f32.tf32.tf32.f32 "               \
        "{%0,%1,%2,%3},{%4,%5,%6,%7},{%8,%9},{%0,%1,%2,%3};"                \
        : "+f"(acc[0]), "+f"(acc[1]), "+f"(acc[2]), "+f"(acc[3])            \
        : "r"(af[0]), "r"(af[1]), "r"(af[2]), "r"(af[3]),                   \
          "r"(bf[0]), "r"(bf[1]))

#define MMA_BF16(acc, af, bf)                                               \
    asm volatile(                                                           \
        "mma.sync.aligned.m16n8k16.row.col.f32.bf16.bf16.f32 "              \
        "{%0,%1,%2,%3},{%4,%5,%6,%7},{%8,%9},{%0,%1,%2,%3};"                \
        : "+f"(acc[0]), "+f"(acc[1]), "+f"(acc[2]), "+f"(acc[3])            \
        : "r"(af[0]), "r"(af[1]), "r"(af[2]), "r"(af[3]),                   \
          "r"(bf[0]), "r"(bf[1]))

__device__ __forceinline__ void ldsm_x4(uint32_t* r, uint32_t a) {
    asm volatile("ldmatrix.sync.aligned.m8n8.x4.shared.b16 {%0,%1,%2,%3},[%4];"
        : "=r"(r[0]), "=r"(r[1]), "=r"(r[2]), "=r"(r[3]) : "r"(a));
}
__device__ __forceinline__ void ldsm_x4t(uint32_t* r, uint32_t a) {
    asm volatile("ldmatrix.sync.aligned.m8n8.x4.trans.shared.b16 {%0,%1,%2,%3},[%4];"
        : "=r"(r[0]), "=r"(r[1]), "=r"(r[2]), "=r"(r[3]) : "r"(a));
}
__device__ __forceinline__ void ldsm_x2(uint32_t* r, uint32_t a) {
    asm volatile("ldmatrix.sync.aligned.m8n8.x2.shared.b16 {%0,%1},[%2];"
        : "=r"(r[0]), "=r"(r[1]) : "r"(a));
}
__device__ __forceinline__ void ldsm_x2t(uint32_t* r, uint32_t a) {
    asm volatile("ldmatrix.sync.aligned.m8n8.x2.trans.shared.b16 {%0,%1},[%2];"
        : "=r"(r[0]), "=r"(r[1]) : "r"(a));
}

__device__ __forceinline__ void cpa16(uint32_t dst, const void* src) {
    asm volatile("cp.async.cg.shared.global [%0], [%1], 16;" :: "r"(dst), "l"(src));
}
#define CP_COMMIT() asm volatile("cp.async.commit_group;" ::: "memory")

__device__ __forceinline__ uint32_t pack2(float a, float b) {
    __nv_bfloat162 h = __floats2bfloat162_rn(a, b);
    return *reinterpret_cast<uint32_t*>(&h);
}

// ---------------- FFMA-pipe exp (~2e-6 rel err) ----------------
__device__ __forceinline__ float fexp(float x)
{
    float t  = fmaxf(x * 1.4426950408889634f, -126.0f);
    float fi = rintf(t);
    float f  = t - fi;
    float p  = 1.3333558146e-3f;
    p = fmaf(p, f, 9.6181291076e-3f);
    p = fmaf(p, f, 5.5504108665e-2f);
    p = fmaf(p, f, 2.4022650696e-1f);
    p = fmaf(p, f, 6.9314718056e-1f);
    p = fmaf(p, f, 1.0f);
    return __int_as_float(__float_as_int(p) + (((int)fi) << 23));
}

// ---------------- x -> bf16 ----------------
__global__ void __launch_bounds__(256)
cvt_x_bf16(const float4* __restrict__ x, uint2* __restrict__ o, int n4)
{
    int i = blockIdx.x * 256 + threadIdx.x;
    if (i >= n4) return;
    float4 v = x[i];
    uint2 r;
    r.x = pack2(v.x, v.y);
    r.y = pack2(v.z, v.w);
    o[i] = r;
}

// ------- weight prep: concat q||k (PAM bf16 / CAM fp32) + wv -> bf16 -------
__global__ void __launch_bounds__(256)
prep_w(const float* __restrict__ pwq, const float* __restrict__ pbq,
       const float* __restrict__ pwk, const float* __restrict__ pbk,
       const float* __restrict__ cwq, const float* __restrict__ cbq,
       const float* __restrict__ cwk, const float* __restrict__ cbk,
       const float* __restrict__ pwv, const float* __restrict__ cwv,
       __nv_bfloat16* __restrict__ wpk, float* __restrict__ bpk,
       float* __restrict__ wck, float* __restrict__ bck,
       __nv_bfloat16* __restrict__ wvp, __nv_bfloat16* __restrict__ wvc)
{
    const int HALF = C8 * CCH;   // 32768
    int i = blockIdx.x * 256 + threadIdx.x;
    if (i < HALF) {
        wpk[i] = __float2bfloat16(pwq[i]);
        wck[i] = cwq[i];
    } else if (i < 2 * HALF) {
        wpk[i] = __float2bfloat16(pwk[i - HALF]);
        wck[i] = cwk[i - HALF];
    }
    for (int j = i; j < CCH * CCH; j += gridDim.x * 256) {
        wvp[j] = __float2bfloat16(pwv[j]);
        wvc[j] = __float2bfloat16(cwv[j]);
    }
    if (i < C8) { bpk[i] = pbq[i]; bck[i] = cbq[i]; }
    else if (i < 2 * C8) { bpk[i] = pbk[i - C8]; bck[i] = cbk[i - C8]; }
}

// =====================================================================
// tf32 GEMM (CAM q/k projection / CAM energy) — unchanged (validated).
// =====================================================================
template<bool TA, bool TB, bool BIASR>
__global__ void __launch_bounds__(256, 2)
gemm_tc_k(const float* __restrict__ A, const float* __restrict__ B,
          const float* __restrict__ bias, float* __restrict__ C,
          int M, int N, int K,
          long long aStr, long long bStr, long long cStr)
{
    constexpr int BK = 16;
    __shared__ uint32_t As[2][BK][128 + 8];
    __shared__ uint32_t Bs[2][BK][128 + 8];

    const float* Ab = A + (long long)blockIdx.z * aStr;
    const float* Bb = B + (long long)blockIdx.z * bStr;
    float*       Cb = C + (long long)blockIdx.z * cStr;
    const int bm = blockIdx.y * 128;
    const int bn = blockIdx.x * 128;

    const int tid = threadIdx.x;
    const int lane = tid & 31;
    const int grp  = lane >> 2;
    const int tig  = lane & 3;
    const int warpId = tid >> 5;
    const int warpM  = warpId >> 2;
    const int warpN  = warpId & 3;

    float acc[4][4][4];
#pragma unroll
    for (int mi = 0; mi < 4; mi++)
#pragma unroll
        for (int ni = 0; ni < 4; ni++)
#pragma unroll
            for (int r = 0; r < 4; r++) acc[mi][ni][r] = 0.0f;

    float4 ra[2], rb[2];

    auto ldA = [&](int k0) {
#pragma unroll
        for (int i = 0; i < 2; i++) {
            int idx = tid + i * 256;
            if (TA) {
                int k = idx >> 5, m4 = idx & 31;
                ra[i] = *reinterpret_cast<const float4*>(Ab + (long long)(k0 + k) * M + bm + m4 * 4);
            } else {
                int m = idx >> 2, k4 = idx & 3;
                ra[i] = *reinterpret_cast<const float4*>(Ab + (long long)(bm + m) * K + k0 + k4 * 4);
            }
        }
    };
    auto stA = [&](int buf) {
#pragma unroll
        for (int i = 0; i < 2; i++) {
            int idx = tid + i * 256;
            float v[4] = {ra[i].x, ra[i].y, ra[i].z, ra[i].w};
            if (TA) {
                int k = idx >> 5, m4 = idx & 31;
#pragma unroll
                for (int j = 0; j < 4; j++) As[buf][k][m4 * 4 + j] = __float_as_uint(v[j]);
            } else {
                int m = idx >> 2, k4 = idx & 3;
#pragma unroll
                for (int j = 0; j < 4; j++) As[buf][k4 * 4 + j][m] = __float_as_uint(v[j]);
            }
        }
    };
    auto ldB = [&](int k0) {
#pragma unroll
        for (int i = 0; i < 2; i++) {
            int idx = tid + i * 256;
            if (TB) {
                int n = idx >> 2, k4 = idx & 3;
                rb[i] = *reinterpret_cast<const float4*>(Bb + (long long)(bn + n) * K + k0 + k4 * 4);
            } else {
                int k = idx >> 5, n4 = idx & 31;
                rb[i] = *reinterpret_cast<const float4*>(Bb + (long long)(k0 + k) * N + bn + n4 * 4);
            }
        }
    };
    auto stB = [&](int buf) {
#pragma unroll
        for (int i = 0; i < 2; i++) {
            int idx = tid + i * 256;
            float v[4] = {rb[i].x, rb[i].y, rb[i].z, rb[i].w};
            if (TB) {
                int n = idx >> 2, k4 = idx & 3;
#pragma unroll
                for (int j = 0; j < 4; j++) Bs[buf][k4 * 4 + j][n] = __float_as_uint(v[j]);
            } else {
                int k = idx >> 5, n4 = idx & 31;
#pragma unroll
                for (int j = 0; j < 4; j++) Bs[buf][k][n4 * 4 + j] = __float_as_uint(v[j]);
            }
        }
    };
    auto compute = [&](int buf) {
#pragma unroll
        for (int ks = 0; ks < BK; ks += 8) {
            uint32_t af[4][4], bf[4][2];
#pragma unroll
            for (int mi = 0; mi < 4; mi++) {
                int mB = warpM * 64 + mi * 16;
                af[mi][0] = As[buf][ks + tig    ][mB + grp];
                af[mi][1] = As[buf][ks + tig    ][mB + grp + 8];
                af[mi][2] = As[buf][ks + tig + 4][mB + grp];
                af[mi][3] = As[buf][ks + tig + 4][mB + grp + 8];
            }
#pragma unroll
            for (int ni = 0; ni < 4; ni++) {
                int nB = warpN * 32 + ni * 8;
                bf[ni][0] = Bs[buf][ks + tig    ][nB + grp];
                bf[ni][1] = Bs[buf][ks + tig + 4][nB + grp];
            }
#pragma unroll
            for (int mi = 0; mi < 4; mi++)
#pragma unroll
                for (int ni = 0; ni < 4; ni++)
                    MMA_TF32(acc[mi][ni], af[mi], bf[ni]);
        }
    };

    const int NT = K / BK;
    ldA(0); ldB(0);
    stA(0); stB(0);
    __syncthreads();
    for (int it = 0; it < NT; ++it) {
        int buf = it & 1;
        if (it + 1 < NT) { ldA((it + 1) * BK); ldB((it + 1) * BK); }
        compute(buf);
        if (it + 1 < NT) { stA(buf ^ 1); stB(buf ^ 1); }
        __syncthreads();
    }

#pragma unroll
    for (int mi = 0; mi < 4; mi++) {
#pragma unroll
        for (int half = 0; half < 2; half++) {
            int gm = bm + warpM * 64 + mi * 16 + grp + half * 8;
            float bv = BIASR ? bias[gm] : 0.0f;
#pragma unroll
            for (int ni = 0; ni < 4; ni++) {
                int gn = bn + warpN * 32 + ni * 8 + tig * 2;
                float vx = acc[mi][ni][half * 2 + 0] + bv;
                float vy = acc[mi][ni][half * 2 + 1] + bv;
                float* crow = Cb + (long long)gm * N;
                *reinterpret_cast<float2*>(&crow[gn]) = make_float2(vx, vy);
            }
        }
    }
}

// =====================================================================
// PAM energy (bf16 MMA) + shifted exp (validated R13-R15).
// =====================================================================
__global__ void __launch_bounds__(256, 2)
pam_energy_b16(const __nv_bfloat16* __restrict__ qp,
               const __nv_bfloat16* __restrict__ kp, long long bstr,
               __nv_bfloat16* __restrict__ Pt, float* __restrict__ gsum)
{
    __shared__ __align__(16) uint32_t As[2][32 * 68];
    __shared__ __align__(16) uint32_t Bs[2][32 * 68];
    __shared__ float sms[4][128];

    const __nv_bfloat16* Ab = qp + (long long)blockIdx.z * bstr;
    const __nv_bfloat16* Bb = kp + (long long)blockIdx.z * bstr;
    const int bm = blockIdx.y * 128;
    const int bn = blockIdx.x * 128;

    const int tid = threadIdx.x;
    const int lane = tid & 31;
    const int grp  = lane >> 2;
    const int tig  = lane & 3;
    const int warpId = tid >> 5;
    const int warpM  = warpId >> 2;
    const int warpN  = warpId & 3;
    const int mB = warpM * 64;
    const int nB = warpN * 32;

    float acc[4][4][4];
#pragma unroll
    for (int mi = 0; mi < 4; mi++)
#pragma unroll
        for (int ni = 0; ni < 4; ni++)
#pragma unroll
            for (int r = 0; r < 4; r++) acc[mi][ni][r] = 0.0f;

    uint32_t aSm[2] = {(uint32_t)__cvta_generic_to_shared(&As[0][0]),
                       (uint32_t)__cvta_generic_to_shared(&As[1][0])};
    uint32_t bSm[2] = {(uint32_t)__cvta_generic_to_shared(&Bs[0][0]),
                       (uint32_t)__cvta_generic_to_shared(&Bs[1][0])};

    auto copyAB = [&](int k0, int buf) {
#pragma unroll
        for (int i = 0; i < 2; i++) {
            int idx = tid + i * 256;
            int k = idx >> 4, m8 = idx & 15;
            cpa16(aSm[buf] + k * 272 + m8 * 16, Ab + (long long)(k0 + k) * NPIX + bm + m8 * 8);
            cpa16(bSm[buf] + k * 272 + m8 * 16, Bb + (long long)(k0 + k) * NPIX + bn + m8 * 8);
        }
    };
    auto compute = [&](int buf) {
#pragma unroll
        for (int c = 0; c < 2; c++) {
            uint32_t af[4][4], bfr[4][2];
#pragma unroll
            for (int mi = 0; mi < 4; mi++) {
                int kr = c * 16 + (lane & 7) + ((lane >> 4) & 1) * 8;
                ldsm_x4t(af[mi], aSm[buf] + kr * 272 + (mB + mi * 16) * 2
                                 + ((lane >> 3) & 1) * 16);
            }
#pragma unroll
            for (int ni = 0; ni < 4; ni++) {
                int kr = c * 16 + (lane & 7) + ((lane >> 3) & 1) * 8;
                ldsm_x2t(bfr[ni], bSm[buf] + kr * 272 + (nB + ni * 8) * 2);
            }
#pragma unroll
            for (int mi = 0; mi < 4; mi++)
#pragma unroll
                for (int ni = 0; ni < 4; ni++)
                    MMA_BF16(acc[mi][ni], af[mi], bfr[ni]);
        }
    };

    copyAB(0, 0);  CP_COMMIT();
    copyAB(32, 1); CP_COMMIT();
    asm volatile("cp.async.wait_group 1;" ::: "memory");
    __syncthreads();
    compute(0);
    asm volatile("cp.async.wait_group 0;" ::: "memory");
    __syncthreads();
    compute(1);

    __nv_bfloat16* Pb = Pt + (long long)blockIdx.z * NPIX * NPIX;
#pragma unroll
    for (int mi = 0; mi < 4; mi++) {
#pragma unroll
        for (int half = 0; half < 2; half++) {
            int rl = warpM * 64 + mi * 16 + grp + half * 8;
            int gm = bm + rl;
            __nv_bfloat16* crow = Pb + (long long)gm * NPIX;
            float part = 0.0f;
#pragma unroll
            for (int ni = 0; ni < 4; ni++) {
                float p0 = fexp(acc[mi][ni][half * 2 + 0] - SHIFT);
                float p1 = fexp(acc[mi][ni][half * 2 + 1] - SHIFT);
                part += p0 + p1;
                int gn = bn + warpN * 32 + ni * 8 + tig * 2;
                *reinterpret_cast<__nv_bfloat162*>(&crow[gn]) =
                    __floats2bfloat162_rn(p0, p1);
            }
            part += __shfl_xor_sync(0xffffffffu, part, 1);
            part += __shfl_xor_sync(0xffffffffu, part, 2);
            if (tig == 0) sms[warpN][rl] = part;
        }
    }
    __syncthreads();
    if (tid < 128) {
        long long o = ((long long)blockIdx.z * NKT + blockIdx.x) * NPIX + bm + tid;
        gsum[o] = sms[0][tid] + sms[1][tid] + sms[2][tid] + sms[3][tid];
    }
}

// =====================================================================
// bf16 GEMM, ldmatrix fragments, 4-stage cp.async pipeline (dyn smem),
// ONE sync per 32-K stage, copies overlapped with MMA.
// =====================================================================
template<bool ATRANS, bool BTRANS, bool BIASR, bool BIASC,
         bool OBF, bool NORM, bool FINAL>
__global__ void __launch_bounds__(256, 2)
gemm_b16(const __nv_bfloat16* __restrict__ A, const __nv_bfloat16* __restrict__ B,
         const float* __restrict__ bias, void* __restrict__ Cgv,
         const float* __restrict__ gsum,
         const float* __restrict__ xres, const float* __restrict__ outp,
         const float* __restrict__ pg, const float* __restrict__ cgam,
         int M, int N, int K,
         long long aStr, long long bStr, long long cStr)
{
    constexpr int APITCH = ATRANS ? 68 : 20;   // uint32 per row
    constexpr int AROWS  = ATRANS ? 32 : 128;
    constexpr int BPITCH = BTRANS ? 68 : 20;
    constexpr int BROWS  = BTRANS ? 32 : 128;
    constexpr int ASZ = AROWS * APITCH;
    constexpr int BSZ = BROWS * BPITCH;

    extern __shared__ __align__(16) uint32_t smem_dyn[];
    uint32_t* AsBase = smem_dyn;
    uint32_t* BsBase = smem_dyn + STG * ASZ;
    float* sm_l = reinterpret_cast<float*>(BsBase + STG * BSZ);

    const __nv_bfloat16* Ab = A + (long long)blockIdx.z * aStr;
    const __nv_bfloat16* Bb = B + (long long)blockIdx.z * bStr;

    const int bm = blockIdx.y * 128;
    const int bn = blockIdx.x * 128;
    const int tid = threadIdx.x;
    const int lane = tid & 31;
    const int grp  = lane >> 2;
    const int tig  = lane & 3;
    const int warpId = tid >> 5;
    const int warpM  = warpId >> 2;
    const int warpN  = warpId & 3;
    const int mB = warpM * 64;
    const int nB = warpN * 32;

    if (NORM) {
        if (tid < 128) {
            const float* gs = gsum + (long long)blockIdx.z * NKT * NPIX + bn + tid;
            float l = 0.0f;
#pragma unroll
            for (int kt = 0; kt < NKT; kt++) l += gs[kt * NPIX];
            sm_l[tid] = 1.0f / l;
        }
    }

    float acc[4][4][4];
#pragma unroll
    for (int mi = 0; mi < 4; mi++)
#pragma unroll
        for (int ni = 0; ni < 4; ni++)
#pragma unroll
            for (int r = 0; r < 4; r++) acc[mi][ni][r] = 0.0f;

    uint32_t aSm[STG], bSm[STG];
#pragma unroll
    for (int s = 0; s < STG; s++) {
        aSm[s] = (uint32_t)__cvta_generic_to_shared(AsBase + s * ASZ);
        bSm[s] = (uint32_t)__cvta_generic_to_shared(BsBase + s * BSZ);
    }

    auto copyAB = [&](int k0, int slot) {
#pragma unroll
        for (int i = 0; i < 2; i++) {
            int idx = tid + i * 256;
            if (ATRANS) {
                int k = idx >> 4, m8 = idx & 15;
                cpa16(aSm[slot] + k * 272 + m8 * 16,
                      Ab + (long long)(k0 + k) * M + bm + m8 * 8);
            } else {
                int m = idx >> 2, kg = idx & 3;
                cpa16(aSm[slot] + m * 80 + kg * 16,
                      Ab + (long long)(bm + m) * K + k0 + kg * 8);
            }
            if (BTRANS) {
                int k = idx >> 4, n8 = idx & 15;
                cpa16(bSm[slot] + k * 272 + n8 * 16,
                      Bb + (long long)(k0 + k) * N + bn + n8 * 8);
            } else {
                int n = idx >> 2, kg = idx & 3;
                cpa16(bSm[slot] + n * 80 + kg * 16,
                      Bb + (long long)(bn + n) * K + k0 + kg * 8);
            }
        }
    };
    auto compute = [&](int slot) {
#pragma unroll
        for (int c = 0; c < 2; c++) {
            uint32_t af[4][4], bfr[4][2];
#pragma unroll
            for (int mi = 0; mi < 4; mi++) {
                if (!ATRANS) {
                    int r = mB + mi * 16 + (lane & 7) + ((lane >> 3) & 1) * 8;
                    ldsm_x4(af[mi], aSm[slot] + r * 80 + c * 32 + ((lane >> 4) & 1) * 16);
                } else {
                    int kr = c * 16 + (lane & 7) + ((lane >> 4) & 1) * 8;
                    ldsm_x4t(af[mi], aSm[slot] + kr * 272 + (mB + mi * 16) * 2
                                     + ((lane >> 3) & 1) * 16);
                }
            }
#pragma unroll
            for (int ni = 0; ni < 4; ni++) {
                if (!BTRANS) {
                    int r = nB + ni * 8 + (lane & 7);
                    ldsm_x2(bfr[ni], bSm[slot] + r * 80 + c * 32 + ((lane >> 3) & 1) * 16);
                } else {
                    int kr = c * 16 + (lane & 7) + ((lane >> 3) & 1) * 8;
                    ldsm_x2t(bfr[ni], bSm[slot] + kr * 272 + (nB + ni * 8) * 2);
                }
            }
#pragma unroll
            for (int mi = 0; mi < 4; mi++)
#pragma unroll
                for (int ni = 0; ni < 4; ni++)
                    MMA_BF16(acc[mi][ni], af[mi], bfr[ni]);
        }
    };

    const int NT = K / 32;
    // prologue: stages 0..STG-2
#pragma unroll
    for (int s = 0; s < STG - 1; s++) {
        if (s < NT) copyAB(s * 32, s);
        CP_COMMIT();
    }
    // steady state: one sync per stage; copy for stage it+STG-1 overlaps compute(it)
    for (int it = 0; it < NT; ++it) {
        asm volatile("cp.async.wait_group %0;" :: "n"(STG - 2) : "memory");
        __syncthreads();
        int nxt = it + STG - 1;
        if (nxt < NT) copyAB(nxt * 32, nxt & (STG - 1));
        CP_COMMIT();
        compute(it & (STG - 1));
    }

    float gpv = 0.f, gcv = 0.f;
    const float* xb = nullptr;
    const float* ob = nullptr;
    if (FINAL) {
        gpv = pg[0]; gcv = cgam[0];
        xb = xres + (long long)blockIdx.z * cStr;
        ob = outp + (long long)blockIdx.z * cStr;
    }

#pragma unroll
    for (int mi = 0; mi < 4; mi++) {
#pragma unroll
        for (int half = 0; half < 2; half++) {
            int gm = bm + warpM * 64 + mi * 16 + grp + half * 8;
            float bv = BIASR ? bias[gm] : 0.0f;
#pragma unroll
            for (int ni = 0; ni < 4; ni++) {
                int gn = bn + warpN * 32 + ni * 8 + tig * 2;
                float vx = acc[mi][ni][half * 2 + 0] + bv;
                float vy = acc[mi][ni][half * 2 + 1] + bv;
                if (BIASC) { vx += bias[gn]; vy += bias[gn + 1]; }
                if (NORM) {
                    vx *= sm_l[gn - bn];
                    vy *= sm_l[gn - bn + 1];
                }
                if (FINAL) {
                    float2 xv = *reinterpret_cast<const float2*>(&xb[(long long)gm * N + gn]);
                    float2 pv = *reinterpret_cast<const float2*>(&ob[(long long)gm * N + gn]);
                    vx = 2.0f * xv.x + gpv * pv.x + gcv * vx;
                    vy = 2.0f * xv.y + gpv * pv.y + gcv * vy;
                }
                if (OBF) {
                    __nv_bfloat16* crow = (__nv_bfloat16*)Cgv
                        + (long long)blockIdx.z * cStr + (long long)gm * N;
                    *reinterpret_cast<__nv_bfloat162*>(&crow[gn]) =
                        __floats2bfloat162_rn(vx, vy);
                } else {
                    float* crow = (float*)Cgv
                        + (long long)blockIdx.z * cStr + (long long)gm * N;
                    *reinterpret_cast<float2*>(&crow[gn]) = make_float2(vx, vy);
                }
            }
        }
    }
}

// -------- CAM row softmax: fp32 in -> bf16 out, softmax(rowmax - e) ----
__global__ void __launch_bounds__(256)
softmax_bf16(const float* __restrict__ in, __nv_bfloat16* __restrict__ out, int n)
{
    __shared__ float buf[512];
    __shared__ float red[8];
    __shared__ float bcast;
    const long long row = blockIdx.x;
    const float* p = in + row * (long long)n;
    const int tid = threadIdx.x;
    const int lane = tid & 31, wid = tid >> 5;

    float m = 3.0e38f;
    for (int i = tid; i < n; i += 256) {
        float v = p[i];
        buf[i] = v;
        m = fminf(m, v);
    }
#pragma unroll
    for (int o = 16; o > 0; o >>= 1)
        m = fminf(m, __shfl_xor_sync(0xffffffffu, m, o));
    if (lane == 0) red[wid] = m;
    __syncthreads();
    if (wid == 0) {
        float v = (lane < 8) ? red[lane] : 3.0e38f;
#pragma unroll
        for (int o = 4; o > 0; o >>= 1)
            v = fminf(v, __shfl_xor_sync(0xffffffffu, v, o));
        if (lane == 0) bcast = v;
    }
    __syncthreads();
    const float mx = bcast;

    float s = 0.0f;
    for (int i = tid; i < n; i += 256) {
        float e = fexp(mx - buf[i]);
        buf[i] = e;
        s += e;
    }
#pragma unroll
    for (int o = 16; o > 0; o >>= 1) s += __shfl_xor_sync(0xffffffffu, s, o);
    if (lane == 0) red[wid] = s;
    __syncthreads();
    if (wid == 0) {
        float v = (lane < 8) ? red[lane] : 0.0f;
#pragma unroll
        for (int o = 4; o > 0; o >>= 1) v += __shfl_xor_sync(0xffffffffu, v, o);
        if (lane == 0) bcast = v;
    }
    __syncthreads();
    const float inv = 1.0f / bcast;
    __nv_bfloat162* o2 = reinterpret_cast<__nv_bfloat162*>(out + row * (long long)n);
    for (int i = tid * 2; i < n; i += 512)
        o2[i >> 1] = __floats2bfloat162_rn(buf[i] * inv, buf[i + 1] * inv);
}

// ---------------- launch ----------------
extern "C" void kernel_launch(void* const* d_in, const int* in_sizes, int n_in,
                              void* d_out, int out_size)
{
    (void)in_sizes; (void)n_in; (void)out_size;
    const float* x       = (const float*)d_in[0];
    const float* pam_wq  = (const float*)d_in[1];
    const float* pam_bq  = (const float*)d_in[2];
    const float* pam_wk  = (const float*)d_in[3];
    const float* pam_bk  = (const float*)d_in[4];
    const float* pam_wv  = (const float*)d_in[5];
    const float* pam_bv  = (const float*)d_in[6];
    const float* pam_g   = (const float*)d_in[7];
    const float* cam_wq  = (const float*)d_in[8];
    const float* cam_bq  = (const float*)d_in[9];
    const float* cam_wk  = (const float*)d_in[10];
    const float* cam_bk  = (const float*)d_in[11];
    const float* cam_wv  = (const float*)d_in[12];
    const float* cam_bv  = (const float*)d_in[13];
    const float* cam_g   = (const float*)d_in[14];

    float *gsum, *ec, *outp, *qkc, *wck, *bck, *bpk;
    __nv_bfloat16 *wpk, *wvp, *wvc, *qkp, *xb16, *vp, *vcT, *pt, *ecb;
    cudaGetSymbolAddress((void**)&gsum, g_sump);
    cudaGetSymbolAddress((void**)&ec,   g_ec);
    cudaGetSymbolAddress((void**)&outp, g_outp);
    cudaGetSymbolAddress((void**)&qkc,  g_qkc);
    cudaGetSymbolAddress((void**)&wck,  g_wck);
    cudaGetSymbolAddress((void**)&bck,  g_bck);
    cudaGetSymbolAddress((void**)&bpk,  g_bpk);
    cudaGetSymbolAddress((void**)&wpk,  g_wpk);
    cudaGetSymbolAddress((void**)&wvp,  g_wvp);
    cudaGetSymbolAddress((void**)&wvc,  g_wvc);
    cudaGetSymbolAddress((void**)&qkp,  g_qkp);
    cudaGetSymbolAddress((void**)&xb16, g_xb);
    cudaGetSymbolAddress((void**)&vp,   g_vp);
    cudaGetSymbolAddress((void**)&vcT,  g_vcT);
    cudaGetSymbolAddress((void**)&pt,   g_pt);
    cudaGetSymbolAddress((void**)&ecb,  g_ecb);

    // dynamic smem sizes (uint32 units -> bytes)
    const int SM_NN = (STG * (128 * 20) * 2) * 4 + 512;   // A,B non-trans (+norm)
    const int SM_NT = (STG * (128 * 20 + 32 * 68)) * 4 + 512;
    static int attr_done = 0;
    if (!attr_done) {
        cudaFuncSetAttribute(
            (const void*)gemm_b16<false, true, true, false, true, false, false>,
            cudaFuncAttributeMaxDynamicSharedMemorySize, SM_NT);
        cudaFuncSetAttribute(
            (const void*)gemm_b16<true, false, false, true, true, false, false>,
            cudaFuncAttributeMaxDynamicSharedMemorySize, SM_NT);
        cudaFuncSetAttribute(
            (const void*)gemm_b16<false, false, false, false, false, true, false>,
            cudaFuncAttributeMaxDynamicSharedMemorySize, SM_NN);
        cudaFuncSetAttribute(
            (const void*)gemm_b16<false, false, false, false, false, false, true>,
            cudaFuncAttributeMaxDynamicSharedMemorySize, SM_NN);
        attr_done = 1;
    }

    const long long xStr   = (long long)CCH * NPIX;
    const long long vStr   = (long long)CCH * NPIX;
    const long long vTStr  = (long long)NPIX * CCH;
    const long long aStrP  = (long long)NPIX * NPIX;
    const long long eStrC  = (long long)CCH * CCH;
    const long long qkStr  = (long long)2 * C8 * NPIX;   // 128*4096

    dim3 blk(256);

    // ---- 0a. x -> bf16 ----
    const int n4 = (BATCH * CCH * NPIX) / 4;
    cvt_x_bf16<<<(n4 + 255) / 256, 256>>>((const float4*)x, (uint2*)xb16, n4);

    // ---- 0b. weight prep (concat q||k + wv->bf16) ----
    prep_w<<<(2 * C8 * CCH) / 256, 256>>>(
        pam_wq, pam_bq, pam_wk, pam_bk,
        cam_wq, cam_bq, cam_wk, cam_bk,
        pam_wv, cam_wv,
        wpk, bpk, wck, bck, wvp, wvc);

    // ---- 1a. PAM q||k projection (bf16, M=128) ----
    gemm_b16<false, true, true, false, true, false, false>
        <<<dim3(NPIX / 128, 1, BATCH), blk, SM_NT>>>(
        wpk, xb16, bpk, qkp, nullptr, nullptr, nullptr, nullptr, nullptr,
        2 * C8, NPIX, CCH, 0, xStr, qkStr);

    // ---- 1b. CAM q||k projection (tf32, M=128) ----
    gemm_tc_k<false, false, true><<<dim3(NPIX / 128, 1, BATCH), blk>>>(
        wck, x, bck, qkc, 2 * C8, NPIX, CCH, 0, xStr, qkStr);

    // ---- 1c. PAM V projection (bf16): vp[C,N] = Wv x ----
    gemm_b16<false, true, true, false, true, false, false>
        <<<dim3(NPIX / 128, CCH / 128, BATCH), blk, SM_NT>>>(
        wvp, xb16, pam_bv, vp, nullptr, nullptr, nullptr, nullptr, nullptr,
        CCH, NPIX, CCH, 0, xStr, vStr);

    // ---- 1d. CAM V projection transposed: vcT[N,C] = x^T Wv^T + b ----
    gemm_b16<true, false, false, true, true, false, false>
        <<<dim3(CCH / 128, NPIX / 128, BATCH), blk, SM_NT>>>(
        xb16, wvc, cam_bv, vcT, nullptr, nullptr, nullptr, nullptr, nullptr,
        NPIX, CCH, CCH, xStr, 0, vTStr);

    // ---- 2. PAM energy (bf16 MMA) + shifted exp -> p~ bf16 + tile sums ----
    pam_energy_b16<<<dim3(NPIX / 128, NPIX / 128, BATCH), blk>>>(
        qkp, qkp + (long long)C8 * NPIX, qkStr, pt, gsum);

    // ---- 3. PAM AV (bf16 NT) with 1/l column scaling ----
    gemm_b16<false, false, false, false, false, true, false>
        <<<dim3(NPIX / 128, CCH / 128, BATCH), blk, SM_NN>>>(
        vp, pt, nullptr, outp, gsum, nullptr, nullptr, nullptr, nullptr,
        CCH, NPIX, NPIX, vStr, aStrP, vStr);

    // ---- 4. CAM energy (NT tf32) ----
    gemm_tc_k<false, true, false><<<dim3(CCH / 128, CCH / 128, BATCH), blk>>>(
        qkc, qkc + (long long)C8 * NPIX, nullptr, ec,
        CCH, CCH, CCH, qkStr, qkStr, eStrC);

    // ---- 5. CAM softmax (flipped) -> bf16 ----
    softmax_bf16<<<BATCH * CCH, 256>>>(ec, ecb, CCH);

    // ---- 6. CAM AV (bf16 NT) + final combine -> d_out ----
    gemm_b16<false, false, false, false, false, false, true>
        <<<dim3(NPIX / 128, CCH / 128, BATCH), blk, SM_NN>>>(
        ecb, vcT, nullptr, d_out, nullptr, x, outp, pam_g, cam_g,
        CCH, NPIX, CCH, eStrC, vTStr, vStr);
}

// round 17
// speedup vs baseline: 1.1536x; 1.1536x over previous
#include <cuda_runtime.h>
#include <cuda_bf16.h>
#include <math.h>
#include <stdint.h>

// ---------------- problem constants ----------------
#define BATCH 4
#define CCH   512
#define C8    64
#define NPIX  4096           // 64*64
#define NKT   32             // key tiles of 128 in PAM
#define SHIFT 16.0f          // fixed softmax shift (energy std ~8, |max|<50)

// ---------------- scratch (device globals; allocation-free) ----------------
__device__ float g_sump[BATCH * NKT * NPIX];
__device__ float g_ec[BATCH * CCH * CCH];                 // CAM energy fp32
__device__ float g_outp[BATCH * CCH * NPIX];              // PAM out (pre-gamma)
__device__ float g_qkc[BATCH * 2 * C8 * NPIX];            // CAM q||k fp32 [128, N]
__device__ float g_wck[2 * C8 * CCH];                     // CAM wq||wk fp32
__device__ float g_bck[2 * C8];
__device__ float g_bpk[2 * C8];
__device__ __nv_bfloat16 g_wpk[2 * C8 * CCH];             // PAM wq||wk bf16
__device__ __nv_bfloat16 g_wvp[CCH * CCH];                // PAM wv bf16
__device__ __nv_bfloat16 g_wvc[CCH * CCH];                // CAM wv bf16
__device__ __nv_bfloat16 g_qkp[BATCH * 2 * C8 * NPIX];    // PAM q||k bf16 [128, N]
__device__ __nv_bfloat16 g_xb [BATCH * CCH * NPIX];       // x in bf16
__device__ __nv_bfloat16 g_vp [BATCH * CCH * NPIX];       // PAM V, [C,N] bf16
__device__ __nv_bfloat16 g_vcT[BATCH * NPIX * CCH];       // CAM V, [N,C] bf16
__device__ __nv_bfloat16 g_pt[(size_t)BATCH * NPIX * NPIX]; // PAM p~ bf16
__device__ __nv_bfloat16 g_ecb[BATCH * CCH * CCH];        // CAM attn bf16

#define MMA_TF32(acc, af, bf)                                               \
    asm volatile(                                                           \
        "mma.sync.aligned.m16n8k8.row.col.f32.tf32.tf32.f32 "               \
        "{%0,%1,%2,%3},{%4,%5,%6,%7},{%8,%9},{%0,%1,%2,%3};"                \
        : "+f"(acc[0]), "+f"(acc[1]), "+f"(acc[2]), "+f"(acc[3])            \
        : "r"(af[0]), "r"(af[1]), "r"(af[2]), "r"(af[3]),                   \
          "r"(bf[0]), "r"(bf[1]))

#define MMA_BF16(acc, af, bf)                                               \
    asm volatile(                                                           \
        "mma.sync.aligned.m16n8k16.row.col.f32.bf16.bf16.f32 "              \
        "{%0,%1,%2,%3},{%4,%5,%6,%7},{%8,%9},{%0,%1,%2,%3};"                \
        : "+f"(acc[0]), "+f"(acc[1]), "+f"(acc[2]), "+f"(acc[3])            \
        : "r"(af[0]), "r"(af[1]), "r"(af[2]), "r"(af[3]),                   \
          "r"(bf[0]), "r"(bf[1]))

__device__ __forceinline__ void ldsm_x4(uint32_t* r, uint32_t a) {
    asm volatile("ldmatrix.sync.aligned.m8n8.x4.shared.b16 {%0,%1,%2,%3},[%4];"
        : "=r"(r[0]), "=r"(r[1]), "=r"(r[2]), "=r"(r[3]) : "r"(a));
}
__device__ __forceinline__ void ldsm_x4t(uint32_t* r, uint32_t a) {
    asm volatile("ldmatrix.sync.aligned.m8n8.x4.trans.shared.b16 {%0,%1,%2,%3},[%4];"
        : "=r"(r[0]), "=r"(r[1]), "=r"(r[2]), "=r"(r[3]) : "r"(a));
}
__device__ __forceinline__ void ldsm_x2(uint32_t* r, uint32_t a) {
    asm volatile("ldmatrix.sync.aligned.m8n8.x2.shared.b16 {%0,%1},[%2];"
        : "=r"(r[0]), "=r"(r[1]) : "r"(a));
}
__device__ __forceinline__ void ldsm_x2t(uint32_t* r, uint32_t a) {
    asm volatile("ldmatrix.sync.aligned.m8n8.x2.trans.shared.b16 {%0,%1},[%2];"
        : "=r"(r[0]), "=r"(r[1]) : "r"(a));
}

__device__ __forceinline__ void cpa16(uint32_t dst, const void* src) {
    asm volatile("cp.async.cg.shared.global [%0], [%1], 16;" :: "r"(dst), "l"(src));
}
#define CP_COMMIT() asm volatile("cp.async.commit_group;" ::: "memory")
#define CP_WAIT1()  asm volatile("cp.async.wait_group 1;" ::: "memory")

__device__ __forceinline__ uint32_t pack2(float a, float b) {
    __nv_bfloat162 h = __floats2bfloat162_rn(a, b);
    return *reinterpret_cast<uint32_t*>(&h);
}

// ---------------- FFMA-pipe exp (~2e-6 rel err) ----------------
__device__ __forceinline__ float fexp(float x)
{
    float t  = fmaxf(x * 1.4426950408889634f, -126.0f);
    float fi = rintf(t);
    float f  = t - fi;
    float p  = 1.3333558146e-3f;
    p = fmaf(p, f, 9.6181291076e-3f);
    p = fmaf(p, f, 5.5504108665e-2f);
    p = fmaf(p, f, 2.4022650696e-1f);
    p = fmaf(p, f, 6.9314718056e-1f);
    p = fmaf(p, f, 1.0f);
    return __int_as_float(__float_as_int(p) + (((int)fi) << 23));
}

// ---------------- x -> bf16 ----------------
__global__ void __launch_bounds__(256)
cvt_x_bf16(const float4* __restrict__ x, uint2* __restrict__ o, int n4)
{
    int i = blockIdx.x * 256 + threadIdx.x;
    if (i >= n4) return;
    float4 v = x[i];
    uint2 r;
    r.x = pack2(v.x, v.y);
    r.y = pack2(v.z, v.w);
    o[i] = r;
}

// ------- weight prep: concat q||k (PAM bf16 / CAM fp32) + wv -> bf16 -------
__global__ void __launch_bounds__(256)
prep_w(const float* __restrict__ pwq, const float* __restrict__ pbq,
       const float* __restrict__ pwk, const float* __restrict__ pbk,
       const float* __restrict__ cwq, const float* __restrict__ cbq,
       const float* __restrict__ cwk, const float* __restrict__ cbk,
       const float* __restrict__ pwv, const float* __restrict__ cwv,
       __nv_bfloat16* __restrict__ wpk, float* __restrict__ bpk,
       float* __restrict__ wck, float* __restrict__ bck,
       __nv_bfloat16* __restrict__ wvp, __nv_bfloat16* __restrict__ wvc)
{
    const int HALF = C8 * CCH;   // 32768
    int i = blockIdx.x * 256 + threadIdx.x;
    if (i < HALF) {
        wpk[i] = __float2bfloat16(pwq[i]);
        wck[i] = cwq[i];
    } else if (i < 2 * HALF) {
        wpk[i] = __float2bfloat16(pwk[i - HALF]);
        wck[i] = cwk[i - HALF];
    }
    for (int j = i; j < CCH * CCH; j += gridDim.x * 256) {
        wvp[j] = __float2bfloat16(pwv[j]);
        wvc[j] = __float2bfloat16(cwv[j]);
    }
    if (i < C8) { bpk[i] = pbq[i]; bck[i] = cbq[i]; }
    else if (i < 2 * C8) { bpk[i] = pbk[i - C8]; bck[i] = cbk[i - C8]; }
}

// =====================================================================
// tf32 GEMM (CAM q/k projection / CAM energy).
// =====================================================================
template<bool TA, bool TB, bool BIASR>
__global__ void __launch_bounds__(256, 2)
gemm_tc_k(const float* __restrict__ A, const float* __restrict__ B,
          const float* __restrict__ bias, float* __restrict__ C,
          int M, int N, int K,
          long long aStr, long long bStr, long long cStr)
{
    constexpr int BK = 16;
    __shared__ uint32_t As[2][BK][128 + 8];
    __shared__ uint32_t Bs[2][BK][128 + 8];

    const float* Ab = A + (long long)blockIdx.z * aStr;
    const float* Bb = B + (long long)blockIdx.z * bStr;
    float*       Cb = C + (long long)blockIdx.z * cStr;
    const int bm = blockIdx.y * 128;
    const int bn = blockIdx.x * 128;

    const int tid = threadIdx.x;
    const int lane = tid & 31;
    const int grp  = lane >> 2;
    const int tig  = lane & 3;
    const int warpId = tid >> 5;
    const int warpM  = warpId >> 2;
    const int warpN  = warpId & 3;

    float acc[4][4][4];
#pragma unroll
    for (int mi = 0; mi < 4; mi++)
#pragma unroll
        for (int ni = 0; ni < 4; ni++)
#pragma unroll
            for (int r = 0; r < 4; r++) acc[mi][ni][r] = 0.0f;

    float4 ra[2], rb[2];

    auto ldA = [&](int k0) {
#pragma unroll
        for (int i = 0; i < 2; i++) {
            int idx = tid + i * 256;
            if (TA) {
                int k = idx >> 5, m4 = idx & 31;
                ra[i] = *reinterpret_cast<const float4*>(Ab + (long long)(k0 + k) * M + bm + m4 * 4);
            } else {
                int m = idx >> 2, k4 = idx & 3;
                ra[i] = *reinterpret_cast<const float4*>(Ab + (long long)(bm + m) * K + k0 + k4 * 4);
            }
        }
    };
    auto stA = [&](int buf) {
#pragma unroll
        for (int i = 0; i < 2; i++) {
            int idx = tid + i * 256;
            float v[4] = {ra[i].x, ra[i].y, ra[i].z, ra[i].w};
            if (TA) {
                int k = idx >> 5, m4 = idx & 31;
#pragma unroll
                for (int j = 0; j < 4; j++) As[buf][k][m4 * 4 + j] = __float_as_uint(v[j]);
            } else {
                int m = idx >> 2, k4 = idx & 3;
#pragma unroll
                for (int j = 0; j < 4; j++) As[buf][k4 * 4 + j][m] = __float_as_uint(v[j]);
            }
        }
    };
    auto ldB = [&](int k0) {
#pragma unroll
        for (int i = 0; i < 2; i++) {
            int idx = tid + i * 256;
            if (TB) {
                int n = idx >> 2, k4 = idx & 3;
                rb[i] = *reinterpret_cast<const float4*>(Bb + (long long)(bn + n) * K + k0 + k4 * 4);
            } else {
                int k = idx >> 5, n4 = idx & 31;
                rb[i] = *reinterpret_cast<const float4*>(Bb + (long long)(k0 + k) * N + bn + n4 * 4);
            }
        }
    };
    auto stB = [&](int buf) {
#pragma unroll
        for (int i = 0; i < 2; i++) {
            int idx = tid + i * 256;
            float v[4] = {rb[i].x, rb[i].y, rb[i].z, rb[i].w};
            if (TB) {
                int n = idx >> 2, k4 = idx & 3;
#pragma unroll
                for (int j = 0; j < 4; j++) Bs[buf][k4 * 4 + j][n] = __float_as_uint(v[j]);
            } else {
                int k = idx >> 5, n4 = idx & 31;
#pragma unroll
                for (int j = 0; j < 4; j++) Bs[buf][k][n4 * 4 + j] = __float_as_uint(v[j]);
            }
        }
    };
    auto compute = [&](int buf) {
#pragma unroll
        for (int ks = 0; ks < BK; ks += 8) {
            uint32_t af[4][4], bf[4][2];
#pragma unroll
            for (int mi = 0; mi < 4; mi++) {
                int mB = warpM * 64 + mi * 16;
                af[mi][0] = As[buf][ks + tig    ][mB + grp];
                af[mi][1] = As[buf][ks + tig    ][mB + grp + 8];
                af[mi][2] = As[buf][ks + tig + 4][mB + grp];
                af[mi][3] = As[buf][ks + tig + 4][mB + grp + 8];
            }
#pragma unroll
            for (int ni = 0; ni < 4; ni++) {
                int nB = warpN * 32 + ni * 8;
                bf[ni][0] = Bs[buf][ks + tig    ][nB + grp];
                bf[ni][1] = Bs[buf][ks + tig + 4][nB + grp];
            }
#pragma unroll
            for (int mi = 0; mi < 4; mi++)
#pragma unroll
                for (int ni = 0; ni < 4; ni++)
                    MMA_TF32(acc[mi][ni], af[mi], bf[ni]);
        }
    };

    const int NT = K / BK;
    ldA(0); ldB(0);
    stA(0); stB(0);
    __syncthreads();
    for (int it = 0; it < NT; ++it) {
        int buf = it & 1;
        if (it + 1 < NT) { ldA((it + 1) * BK); ldB((it + 1) * BK); }
        compute(buf);
        if (it + 1 < NT) { stA(buf ^ 1); stB(buf ^ 1); }
        __syncthreads();
    }

#pragma unroll
    for (int mi = 0; mi < 4; mi++) {
#pragma unroll
        for (int half = 0; half < 2; half++) {
            int gm = bm + warpM * 64 + mi * 16 + grp + half * 8;
            float bv = BIASR ? bias[gm] : 0.0f;
#pragma unroll
            for (int ni = 0; ni < 4; ni++) {
                int gn = bn + warpN * 32 + ni * 8 + tig * 2;
                float vx = acc[mi][ni][half * 2 + 0] + bv;
                float vy = acc[mi][ni][half * 2 + 1] + bv;
                float* crow = Cb + (long long)gm * N;
                *reinterpret_cast<float2*>(&crow[gn]) = make_float2(vx, vy);
            }
        }
    }
}

// =====================================================================
// PAM energy (bf16 MMA) + shifted exp (validated R13-R15).
// =====================================================================
__global__ void __launch_bounds__(256, 2)
pam_energy_b16(const __nv_bfloat16* __restrict__ qp,
               const __nv_bfloat16* __restrict__ kp, long long bstr,
               __nv_bfloat16* __restrict__ Pt, float* __restrict__ gsum)
{
    __shared__ __align__(16) uint32_t As[2][32 * 68];
    __shared__ __align__(16) uint32_t Bs[2][32 * 68];
    __shared__ float sms[4][128];

    const __nv_bfloat16* Ab = qp + (long long)blockIdx.z * bstr;
    const __nv_bfloat16* Bb = kp + (long long)blockIdx.z * bstr;
    const int bm = blockIdx.y * 128;
    const int bn = blockIdx.x * 128;

    const int tid = threadIdx.x;
    const int lane = tid & 31;
    const int grp  = lane >> 2;
    const int tig  = lane & 3;
    const int warpId = tid >> 5;
    const int warpM  = warpId >> 2;
    const int warpN  = warpId & 3;
    const int mB = warpM * 64;
    const int nB = warpN * 32;

    float acc[4][4][4];
#pragma unroll
    for (int mi = 0; mi < 4; mi++)
#pragma unroll
        for (int ni = 0; ni < 4; ni++)
#pragma unroll
            for (int r = 0; r < 4; r++) acc[mi][ni][r] = 0.0f;

    uint32_t aSm[2] = {(uint32_t)__cvta_generic_to_shared(&As[0][0]),
                       (uint32_t)__cvta_generic_to_shared(&As[1][0])};
    uint32_t bSm[2] = {(uint32_t)__cvta_generic_to_shared(&Bs[0][0]),
                       (uint32_t)__cvta_generic_to_shared(&Bs[1][0])};

    auto copyAB = [&](int k0, int buf) {
#pragma unroll
        for (int i = 0; i < 2; i++) {
            int idx = tid + i * 256;
            int k = idx >> 4, m8 = idx & 15;
            cpa16(aSm[buf] + k * 272 + m8 * 16, Ab + (long long)(k0 + k) * NPIX + bm + m8 * 8);
            cpa16(bSm[buf] + k * 272 + m8 * 16, Bb + (long long)(k0 + k) * NPIX + bn + m8 * 8);
        }
    };
    auto compute = [&](int buf) {
#pragma unroll
        for (int c = 0; c < 2; c++) {
            uint32_t af[4][4], bfr[4][2];
#pragma unroll
            for (int mi = 0; mi < 4; mi++) {
                int kr = c * 16 + (lane & 7) + ((lane >> 4) & 1) * 8;
                ldsm_x4t(af[mi], aSm[buf] + kr * 272 + (mB + mi * 16) * 2
                                 + ((lane >> 3) & 1) * 16);
            }
#pragma unroll
            for (int ni = 0; ni < 4; ni++) {
                int kr = c * 16 + (lane & 7) + ((lane >> 3) & 1) * 8;
                ldsm_x2t(bfr[ni], bSm[buf] + kr * 272 + (nB + ni * 8) * 2);
            }
#pragma unroll
            for (int mi = 0; mi < 4; mi++)
#pragma unroll
                for (int ni = 0; ni < 4; ni++)
                    MMA_BF16(acc[mi][ni], af[mi], bfr[ni]);
        }
    };

    copyAB(0, 0);  CP_COMMIT();
    copyAB(32, 1); CP_COMMIT();
    CP_WAIT1(); __syncthreads();
    compute(0);
    asm volatile("cp.async.wait_group 0;" ::: "memory");
    __syncthreads();
    compute(1);

    __nv_bfloat16* Pb = Pt + (long long)blockIdx.z * NPIX * NPIX;
#pragma unroll
    for (int mi = 0; mi < 4; mi++) {
#pragma unroll
        for (int half = 0; half < 2; half++) {
            int rl = warpM * 64 + mi * 16 + grp + half * 8;
            int gm = bm + rl;
            __nv_bfloat16* crow = Pb + (long long)gm * NPIX;
            float part = 0.0f;
#pragma unroll
            for (int ni = 0; ni < 4; ni++) {
                float p0 = fexp(acc[mi][ni][half * 2 + 0] - SHIFT);
                float p1 = fexp(acc[mi][ni][half * 2 + 1] - SHIFT);
                part += p0 + p1;
                int gn = bn + warpN * 32 + ni * 8 + tig * 2;
                *reinterpret_cast<__nv_bfloat162*>(&crow[gn]) =
                    __floats2bfloat162_rn(p0, p1);
            }
            part += __shfl_xor_sync(0xffffffffu, part, 1);
            part += __shfl_xor_sync(0xffffffffu, part, 2);
            if (tig == 0) sms[warpN][rl] = part;
        }
    }
    __syncthreads();
    if (tid < 128) {
        long long o = ((long long)blockIdx.z * NKT + blockIdx.x) * NPIX + bm + tid;
        gsum[o] = sms[0][tid] + sms[1][tid] + sms[2][tid] + sms[3][tid];
    }
}

// =====================================================================
// bf16 GEMM, ldmatrix fragments, 2-stage cp.async pipeline (R15, proven).
// =====================================================================
template<bool ATRANS, bool BTRANS, bool BIASR, bool BIASC,
         bool OBF, bool NORM, bool FINAL>
__global__ void __launch_bounds__(256, 2)
gemm_b16(const __nv_bfloat16* __restrict__ A, const __nv_bfloat16* __restrict__ B,
         const float* __restrict__ bias, void* __restrict__ Cgv,
         const float* __restrict__ gsum,
         const float* __restrict__ xres, const float* __restrict__ outp,
         const float* __restrict__ pg, const float* __restrict__ cgam,
         int M, int N, int K,
         long long aStr, long long bStr, long long cStr)
{
    constexpr int APITCH = ATRANS ? 68 : 20;
    constexpr int AROWS  = ATRANS ? 32 : 128;
    constexpr int BPITCH = BTRANS ? 68 : 20;
    constexpr int BROWS  = BTRANS ? 32 : 128;
    __shared__ __align__(16) uint32_t As[2][AROWS * APITCH];
    __shared__ __align__(16) uint32_t Bs[2][BROWS * BPITCH];
    __shared__ float sm_l[NORM ? 128 : 1];

    const __nv_bfloat16* Ab = A + (long long)blockIdx.z * aStr;
    const __nv_bfloat16* Bb = B + (long long)blockIdx.z * bStr;

    const int bm = blockIdx.y * 128;
    const int bn = blockIdx.x * 128;
    const int tid = threadIdx.x;
    const int lane = tid & 31;
    const int grp  = lane >> 2;
    const int tig  = lane & 3;
    const int warpId = tid >> 5;
    const int warpM  = warpId >> 2;
    const int warpN  = warpId & 3;
    const int mB = warpM * 64;
    const int nB = warpN * 32;

    if (NORM) {
        if (tid < 128) {
            const float* gs = gsum + (long long)blockIdx.z * NKT * NPIX + bn + tid;
            float l = 0.0f;
#pragma unroll
            for (int kt = 0; kt < NKT; kt++) l += gs[kt * NPIX];
            sm_l[tid] = 1.0f / l;
        }
    }

    float acc[4][4][4];
#pragma unroll
    for (int mi = 0; mi < 4; mi++)
#pragma unroll
        for (int ni = 0; ni < 4; ni++)
#pragma unroll
            for (int r = 0; r < 4; r++) acc[mi][ni][r] = 0.0f;

    uint32_t aSm[2] = {(uint32_t)__cvta_generic_to_shared(&As[0][0]),
                       (uint32_t)__cvta_generic_to_shared(&As[1][0])};
    uint32_t bSm[2] = {(uint32_t)__cvta_generic_to_shared(&Bs[0][0]),
                       (uint32_t)__cvta_generic_to_shared(&Bs[1][0])};

    auto copyA = [&](int k0, int buf) {
#pragma unroll
        for (int i = 0; i < 2; i++) {
            int idx = tid + i * 256;
            if (ATRANS) {
                int k = idx >> 4, m8 = idx & 15;
                cpa16(aSm[buf] + k * 272 + m8 * 16,
                      Ab + (long long)(k0 + k) * M + bm + m8 * 8);
            } else {
                int m = idx >> 2, kg = idx & 3;
                cpa16(aSm[buf] + m * 80 + kg * 16,
                      Ab + (long long)(bm + m) * K + k0 + kg * 8);
            }
        }
    };
    auto copyB = [&](int k0, int buf) {
#pragma unroll
        for (int i = 0; i < 2; i++) {
            int idx = tid + i * 256;
            if (BTRANS) {
                int k = idx >> 4, n8 = idx & 15;
                cpa16(bSm[buf] + k * 272 + n8 * 16,
                      Bb + (long long)(k0 + k) * N + bn + n8 * 8);
            } else {
                int n = idx >> 2, kg = idx & 3;
                cpa16(bSm[buf] + n * 80 + kg * 16,
                      Bb + (long long)(bn + n) * K + k0 + kg * 8);
            }
        }
    };
    auto compute = [&](int buf) {
#pragma unroll
        for (int c = 0; c < 2; c++) {
            uint32_t af[4][4], bfr[4][2];
#pragma unroll
            for (int mi = 0; mi < 4; mi++) {
                if (!ATRANS) {
                    int r = mB + mi * 16 + (lane & 7) + ((lane >> 3) & 1) * 8;
                    ldsm_x4(af[mi], aSm[buf] + r * 80 + c * 32 + ((lane >> 4) & 1) * 16);
                } else {
                    int kr = c * 16 + (lane & 7) + ((lane >> 4) & 1) * 8;
                    ldsm_x4t(af[mi], aSm[buf] + kr * 272 + (mB + mi * 16) * 2
                                     + ((lane >> 3) & 1) * 16);
                }
            }
#pragma unroll
            for (int ni = 0; ni < 4; ni++) {
                if (!BTRANS) {
                    int r = nB + ni * 8 + (lane & 7);
                    ldsm_x2(bfr[ni], bSm[buf] + r * 80 + c * 32 + ((lane >> 3) & 1) * 16);
                } else {
                    int kr = c * 16 + (lane & 7) + ((lane >> 3) & 1) * 8;
                    ldsm_x2t(bfr[ni], bSm[buf] + kr * 272 + (nB + ni * 8) * 2);
                }
            }
#pragma unroll
            for (int mi = 0; mi < 4; mi++)
#pragma unroll
                for (int ni = 0; ni < 4; ni++)
                    MMA_BF16(acc[mi][ni], af[mi], bfr[ni]);
        }
    };

    const int NT = K / 32;
    copyA(0, 0); copyB(0, 0); CP_COMMIT();
    if (NT > 1) { copyA(32, 1); copyB(32, 1); }
    CP_COMMIT();
    for (int it = 0; it < NT; ++it) {
        CP_WAIT1();
        __syncthreads();
        compute(it & 1);
        __syncthreads();
        if (it + 2 < NT) { copyA((it + 2) * 32, it & 1); copyB((it + 2) * 32, it & 1); }
        CP_COMMIT();
    }

    float gpv = 0.f, gcv = 0.f;
    const float* xb = nullptr;
    const float* ob = nullptr;
    if (FINAL) {
        gpv = pg[0]; gcv = cgam[0];
        xb = xres + (long long)blockIdx.z * cStr;
        ob = outp + (long long)blockIdx.z * cStr;
    }

#pragma unroll
    for (int mi = 0; mi < 4; mi++) {
#pragma unroll
        for (int half = 0; half < 2; half++) {
            int gm = bm + warpM * 64 + mi * 16 + grp + half * 8;
            float bv = BIASR ? bias[gm] : 0.0f;
#pragma unroll
            for (int ni = 0; ni < 4; ni++) {
                int gn = bn + warpN * 32 + ni * 8 + tig * 2;
                float vx = acc[mi][ni][half * 2 + 0] + bv;
                float vy = acc[mi][ni][half * 2 + 1] + bv;
                if (BIASC) { vx += bias[gn]; vy += bias[gn + 1]; }
                if (NORM) {
                    vx *= sm_l[gn - bn];
                    vy *= sm_l[gn - bn + 1];
                }
                if (FINAL) {
                    float2 xv = *reinterpret_cast<const float2*>(&xb[(long long)gm * N + gn]);
                    float2 pv = *reinterpret_cast<const float2*>(&ob[(long long)gm * N + gn]);
                    vx = 2.0f * xv.x + gpv * pv.x + gcv * vx;
                    vy = 2.0f * xv.y + gpv * pv.y + gcv * vy;
                }
                if (OBF) {
                    __nv_bfloat16* crow = (__nv_bfloat16*)Cgv
                        + (long long)blockIdx.z * cStr + (long long)gm * N;
                    *reinterpret_cast<__nv_bfloat162*>(&crow[gn]) =
                        __floats2bfloat162_rn(vx, vy);
                } else {
                    float* crow = (float*)Cgv
                        + (long long)blockIdx.z * cStr + (long long)gm * N;
                    *reinterpret_cast<float2*>(&crow[gn]) = make_float2(vx, vy);
                }
            }
        }
    }
}

// -------- CAM row softmax: fp32 in -> bf16 out, softmax(rowmax - e) ----
__global__ void __launch_bounds__(256)
softmax_bf16(const float* __restrict__ in, __nv_bfloat16* __restrict__ out, int n)
{
    __shared__ float buf[512];
    __shared__ float red[8];
    __shared__ float bcast;
    const long long row = blockIdx.x;
    const float* p = in + row * (long long)n;
    const int tid = threadIdx.x;
    const int lane = tid & 31, wid = tid >> 5;

    float m = 3.0e38f;
    for (int i = tid; i < n; i += 256) {
        float v = p[i];
        buf[i] = v;
        m = fminf(m, v);
    }
#pragma unroll
    for (int o = 16; o > 0; o >>= 1)
        m = fminf(m, __shfl_xor_sync(0xffffffffu, m, o));
    if (lane == 0) red[wid] = m;
    __syncthreads();
    if (wid == 0) {
        float v = (lane < 8) ? red[lane] : 3.0e38f;
#pragma unroll
        for (int o = 4; o > 0; o >>= 1)
            v = fminf(v, __shfl_xor_sync(0xffffffffu, v, o));
        if (lane == 0) bcast = v;
    }
    __syncthreads();
    const float mx = bcast;

    float s = 0.0f;
    for (int i = tid; i < n; i += 256) {
        float e = fexp(mx - buf[i]);
        buf[i] = e;
        s += e;
    }
#pragma unroll
    for (int o = 16; o > 0; o >>= 1) s += __shfl_xor_sync(0xffffffffu, s, o);
    if (lane == 0) red[wid] = s;
    __syncthreads();
    if (wid == 0) {
        float v = (lane < 8) ? red[lane] : 0.0f;
#pragma unroll
        for (int o = 4; o > 0; o >>= 1) v += __shfl_xor_sync(0xffffffffu, v, o);
        if (lane == 0) bcast = v;
    }
    __syncthreads();
    const float inv = 1.0f / bcast;
    __nv_bfloat162* o2 = reinterpret_cast<__nv_bfloat162*>(out + row * (long long)n);
    for (int i = tid * 2; i < n; i += 512)
        o2[i >> 1] = __floats2bfloat162_rn(buf[i] * inv, buf[i + 1] * inv);
}

// ---------------- launch ----------------
extern "C" void kernel_launch(void* const* d_in, const int* in_sizes, int n_in,
                              void* d_out, int out_size)
{
    (void)in_sizes; (void)n_in; (void)out_size;
    const float* x       = (const float*)d_in[0];
    const float* pam_wq  = (const float*)d_in[1];
    const float* pam_bq  = (const float*)d_in[2];
    const float* pam_wk  = (const float*)d_in[3];
    const float* pam_bk  = (const float*)d_in[4];
    const float* pam_wv  = (const float*)d_in[5];
    const float* pam_bv  = (const float*)d_in[6];
    const float* pam_g   = (const float*)d_in[7];
    const float* cam_wq  = (const float*)d_in[8];
    const float* cam_bq  = (const float*)d_in[9];
    const float* cam_wk  = (const float*)d_in[10];
    const float* cam_bk  = (const float*)d_in[11];
    const float* cam_wv  = (const float*)d_in[12];
    const float* cam_bv  = (const float*)d_in[13];
    const float* cam_g   = (const float*)d_in[14];

    float *gsum, *ec, *outp, *qkc, *wck, *bck, *bpk;
    __nv_bfloat16 *wpk, *wvp, *wvc, *qkp, *xb16, *vp, *vcT, *pt, *ecb;
    cudaGetSymbolAddress((void**)&gsum, g_sump);
    cudaGetSymbolAddress((void**)&ec,   g_ec);
    cudaGetSymbolAddress((void**)&outp, g_outp);
    cudaGetSymbolAddress((void**)&qkc,  g_qkc);
    cudaGetSymbolAddress((void**)&wck,  g_wck);
    cudaGetSymbolAddress((void**)&bck,  g_bck);
    cudaGetSymbolAddress((void**)&bpk,  g_bpk);
    cudaGetSymbolAddress((void**)&wpk,  g_wpk);
    cudaGetSymbolAddress((void**)&wvp,  g_wvp);
    cudaGetSymbolAddress((void**)&wvc,  g_wvc);
    cudaGetSymbolAddress((void**)&qkp,  g_qkp);
    cudaGetSymbolAddress((void**)&xb16, g_xb);
    cudaGetSymbolAddress((void**)&vp,   g_vp);
    cudaGetSymbolAddress((void**)&vcT,  g_vcT);
    cudaGetSymbolAddress((void**)&pt,   g_pt);
    cudaGetSymbolAddress((void**)&ecb,  g_ecb);

    // side stream + events, created once on the first (uncaptured) call
    static cudaStream_t s2 = nullptr;
    static cudaEvent_t evFork = nullptr, evJoin = nullptr;
    if (!s2) {
        cudaStreamCreateWithFlags(&s2, cudaStreamNonBlocking);
        cudaEventCreateWithFlags(&evFork, cudaEventDisableTiming);
        cudaEventCreateWithFlags(&evJoin, cudaEventDisableTiming);
    }

    const long long xStr   = (long long)CCH * NPIX;
    const long long vStr   = (long long)CCH * NPIX;
    const long long vTStr  = (long long)NPIX * CCH;
    const long long aStrP  = (long long)NPIX * NPIX;
    const long long eStrC  = (long long)CCH * CCH;
    const long long qkStr  = (long long)2 * C8 * NPIX;   // 128*4096

    dim3 blk(256);

    // ---- 0a. x -> bf16 (default stream) ----
    const int n4 = (BATCH * CCH * NPIX) / 4;
    cvt_x_bf16<<<(n4 + 255) / 256, 256>>>((const float4*)x, (uint2*)xb16, n4);

    // ---- 0b. weight prep ----
    prep_w<<<(2 * C8 * CCH) / 256, 256>>>(
        pam_wq, pam_bq, pam_wk, pam_bk,
        cam_wq, cam_bq, cam_wk, cam_bk,
        pam_wv, cam_wv,
        wpk, bpk, wck, bck, wvp, wvc);

    // ======== fork: CAM chain on s2, PAM chain on default ========
    cudaEventRecord(evFork, 0);
    cudaStreamWaitEvent(s2, evFork, 0);

    // ---- CAM q||k projection (tf32, M=128)  [s2] ----
    gemm_tc_k<false, false, true><<<dim3(NPIX / 128, 1, BATCH), blk, 0, s2>>>(
        wck, x, bck, qkc, 2 * C8, NPIX, CCH, 0, xStr, qkStr);

    // ---- CAM V projection transposed: vcT[N,C]  [s2] ----
    gemm_b16<true, false, false, true, true, false, false>
        <<<dim3(CCH / 128, NPIX / 128, BATCH), blk, 0, s2>>>(
        xb16, wvc, cam_bv, vcT, nullptr, nullptr, nullptr, nullptr, nullptr,
        NPIX, CCH, CCH, xStr, 0, vTStr);

    // ---- CAM energy (NT tf32)  [s2] ----
    gemm_tc_k<false, true, false><<<dim3(CCH / 128, CCH / 128, BATCH), blk, 0, s2>>>(
        qkc, qkc + (long long)C8 * NPIX, nullptr, ec,
        CCH, CCH, CCH, qkStr, qkStr, eStrC);

    // ---- CAM softmax (flipped) -> bf16  [s2] ----
    softmax_bf16<<<BATCH * CCH, 256, 0, s2>>>(ec, ecb, CCH);

    cudaEventRecord(evJoin, s2);

    // ---- PAM q||k projection (bf16, M=128)  [default] ----
    gemm_b16<false, true, true, false, true, false, false>
        <<<dim3(NPIX / 128, 1, BATCH), blk>>>(
        wpk, xb16, bpk, qkp, nullptr, nullptr, nullptr, nullptr, nullptr,
        2 * C8, NPIX, CCH, 0, xStr, qkStr);

    // ---- PAM V projection (bf16): vp[C,N]  [default] ----
    gemm_b16<false, true, true, false, true, false, false>
        <<<dim3(NPIX / 128, CCH / 128, BATCH), blk>>>(
        wvp, xb16, pam_bv, vp, nullptr, nullptr, nullptr, nullptr, nullptr,
        CCH, NPIX, CCH, 0, xStr, vStr);

    // ---- PAM energy (bf16 MMA) + shifted exp  [default] ----
    pam_energy_b16<<<dim3(NPIX / 128, NPIX / 128, BATCH), blk>>>(
        qkp, qkp + (long long)C8 * NPIX, qkStr, pt, gsum);

    // ---- PAM AV (bf16 NT) with 1/l column scaling  [default] ----
    gemm_b16<false, false, false, false, false, true, false>
        <<<dim3(NPIX / 128, CCH / 128, BATCH), blk>>>(
        vp, pt, nullptr, outp, gsum, nullptr, nullptr, nullptr, nullptr,
        CCH, NPIX, NPIX, vStr, aStrP, vStr);

    // ======== join ========
    cudaStreamWaitEvent(0, evJoin, 0);

    // ---- CAM AV (bf16 NT) + final combine -> d_out  [default] ----
    gemm_b16<false, false, false, false, false, false, true>
        <<<dim3(NPIX / 128, CCH / 128, BATCH), blk>>>(
        ecb, vcT, nullptr, d_out, nullptr, x, outp, pam_g, cam_g,
        CCH, NPIX, CCH, eStrC, vTStr, vStr);
}